// round 15
// baseline (speedup 1.0000x reference)
#include <cuda_runtime.h>
#include <cstdint>

#define NSLOPE 0.2f
#define NMAX   50048
#define EMAX   655360

// ---- device scratch (no runtime allocation allowed) ----
__device__ float g_h[NMAX * 128];     // h = in @ W (fp32)
__device__ float g_ah[NMAX * 128];    // A-operand hi tf32 plane (pair-permuted)
__device__ float g_al[NMAX * 128];    // A-operand lo tf32 plane (pair-permuted)
__device__ float g_o2[NMAX * 64];     // final pre-log-softmax
__device__ float g_as[NMAX];          // h . a_src per node
__device__ float g_ad[NMAX];          // h . a_dst per node
__device__ int   g_deg[NMAX];         // in-degree (w/o self loop)
__device__ int   g_start[NMAX];       // CSR segment start (by dst)
__device__ int   g_cur[NMAX];         // scatter cursors
__device__ int   g_csr[EMAX];         // src node per CSR slot
__device__ int   g_cnt;               // global slot allocator

#define TF32_RND(u, f) asm("cvt.rna.tf32.f32 %0, %1;" : "=r"(u) : "f"(f))

__device__ __forceinline__ void split2(float v, float& hi, float& lo) {
    uint32_t hb;
    TF32_RND(hb, v);
    hi = __uint_as_float(hb);
    uint32_t lb;
    TF32_RND(lb, v - hi);
    lo = __uint_as_float(lb);
}

// m16n8k8 tf32 HMMA, C += A*B (row.col)
__device__ __forceinline__ void mma8(float* c, const uint32_t* a, uint32_t b0, uint32_t b1) {
    asm volatile(
        "mma.sync.aligned.m16n8k8.row.col.f32.tf32.tf32.f32 "
        "{%0,%1,%2,%3}, {%4,%5,%6,%7}, {%8,%9}, {%0,%1,%2,%3};"
        : "+f"(c[0]), "+f"(c[1]), "+f"(c[2]), "+f"(c[3])
        : "r"(a[0]), "r"(a[1]), "r"(a[2]), "r"(a[3]), "r"(b0), "r"(b1));
}

// ============== x -> pair-permuted tf32 hi/lo planes ==============
// slot(col c) = (c>>3)*8 + (c&3)*2 + ((c>>2)&1): pairs (c, c+4) adjacent.

__global__ void k_cvt(const float* __restrict__ x, float* __restrict__ ah,
                      float* __restrict__ al, int n) {
    int i = blockIdx.x * 256 + threadIdx.x;
    if (i >= n * 16) return;
    int r = i >> 4, g = i & 15;
    const float* xp = x + (size_t)r * 128 + g * 8;
    float4 v0 = *(const float4*)xp;
    float4 v1 = *(const float4*)(xp + 4);
    float vv[8] = {v0.x, v0.y, v0.z, v0.w, v1.x, v1.y, v1.z, v1.w};
    float hi[8], lo[8];
#pragma unroll
    for (int j = 0; j < 8; j++) split2(vv[j], hi[j], lo[j]);
    size_t o = (size_t)r * 128 + g * 8;
    *(float4*)(ah + o)     = make_float4(hi[0], hi[4], hi[1], hi[5]);
    *(float4*)(ah + o + 4) = make_float4(hi[2], hi[6], hi[3], hi[7]);
    *(float4*)(al + o)     = make_float4(lo[0], lo[4], lo[1], lo[5]);
    *(float4*)(al + o + 4) = make_float4(lo[2], lo[6], lo[3], lo[7]);
}

// ========================== CSR build ==========================

__global__ void k_zero(int n) {
    int i = blockIdx.x * 256 + threadIdx.x;
    if (i < n) g_deg[i] = 0;
    if (i == 0) g_cnt = 0;
}

__global__ void k_count(const int* __restrict__ dst, int e) {
    int i = blockIdx.x * 256 + threadIdx.x;
    if (i < e) atomicAdd(&g_deg[dst[i]], 1);
}

__global__ void k_alloc(int n) {
    __shared__ int s[256];
    __shared__ int base;
    int tid = threadIdx.x;
    int i = blockIdx.x * 256 + tid;
    int deg = (i < n) ? g_deg[i] + 1 : 0;  // +1 self loop
    s[tid] = deg;
    __syncthreads();
    for (int off = 1; off < 256; off <<= 1) {
        int a = s[tid];
        int b = (tid >= off) ? s[tid - off] : 0;
        __syncthreads();
        s[tid] = a + b;
        __syncthreads();
    }
    if (tid == 255) base = atomicAdd(&g_cnt, s[255]);
    __syncthreads();
    if (i < n) {
        int st = base + s[tid] - deg;
        g_start[i] = st;
        g_csr[st] = i;   // self-loop occupies slot 0
        g_cur[i] = 1;
    }
}

__global__ void k_scatter(const int* __restrict__ src, const int* __restrict__ dst, int e) {
    int i = blockIdx.x * 256 + threadIdx.x;
    if (i < e) {
        int d = dst[i];
        int p = atomicAdd(&g_cur[d], 1);
        g_csr[g_start[d] + p] = src[i];
    }
}

// ============ mma.sync 3xTF32 GEMM, lean data path ============
// H[M,BN] = A[M,128] @ W[128,BN]. A comes pre-split (Ah/Al pair-permuted gmem).
// W split+permuted once per block into smem (frag-contiguous, conflict-free
// LDS.128). Mainloop: 16 k-steps, zero syncs, A prefetched one step ahead.
// Block 256 thr = 8 warps (4 wm x 2 wn), tile 128 x BN.

template <int BN>
__global__ __launch_bounds__(256) void k_tc(
    const float* __restrict__ Ah, const float* __restrict__ Al,
    const float* __restrict__ W, float* __restrict__ H,
    const float* __restrict__ a_s, const float* __restrict__ a_d, int M)
{
    constexpr int NT   = BN / 16;        // N-tiles per warp (8 or 4)
    constexpr int STRD = 2 * NT + 4;     // lane stride (20 or 12): conflict-free LDS.128
    constexpr int PL   = 2 * 16 * 32 * STRD;  // floats per plane

    extern __shared__ float sw[];
    float* Wh = sw;
    float* Wl = sw + PL;
    __shared__ float s_sa[128], s_sd[128];

    int tid = threadIdx.x, wid = tid >> 5, lane = tid & 31;
    int wm = wid >> 1, wn = wid & 1;
    int lr = lane >> 2, lk = lane & 3;
    int row0 = blockIdx.x * 128;

    // ---- stage W once: split + fragment-permute ----
    for (int i = tid; i < 128 * BN / 4; i += 256) {
        int k = i / (BN / 4);
        int n4 = (i % (BN / 4)) * 4;
        float4 v = *(const float4*)(W + (size_t)k * BN + n4);
        float vv[4] = {v.x, v.y, v.z, v.w};
        int lkk = k & 3, half = (k >> 2) & 1, ks = k >> 3;
#pragma unroll
        for (int j = 0; j < 4; j++) {
            int nn = n4 + j;
            int wnn = nn / (BN / 2), np = nn % (BN / 2);
            int idx = ((wnn * 16 + ks) * 32 + ((np & 7) * 4 + lkk)) * STRD + (np >> 3) * 2 + half;
            float hi, lo;
            split2(vv[j], hi, lo);
            Wh[idx] = hi;
            Wl[idx] = lo;
        }
    }
    if (tid < 128) {
        s_sa[tid] = 0.f;
        s_sd[tid] = 0.f;
    }
    __syncthreads();

    float c[2][NT][4];
#pragma unroll
    for (int t = 0; t < 2; t++)
#pragma unroll
        for (int nt = 0; nt < NT; nt++)
#pragma unroll
            for (int q = 0; q < 4; q++) c[t][nt][q] = 0.f;

    int rA0 = row0 + wm * 32 + lr;
    const float* pAh = Ah + (size_t)rA0 * 128 + lk * 2;
    const float* pAl = Al + (size_t)rA0 * 128 + lk * 2;

    float2 nh[4], nl[4];
    {
        nh[0] = *(const float2*)(pAh);
        nh[1] = *(const float2*)(pAh + 8 * 128);
        nh[2] = *(const float2*)(pAh + 16 * 128);
        nh[3] = *(const float2*)(pAh + 24 * 128);
        nl[0] = *(const float2*)(pAl);
        nl[1] = *(const float2*)(pAl + 8 * 128);
        nl[2] = *(const float2*)(pAl + 16 * 128);
        nl[3] = *(const float2*)(pAl + 24 * 128);
    }

#pragma unroll
    for (int ks = 0; ks < 16; ks++) {
        float2 chh[4], cll[4];
#pragma unroll
        for (int q = 0; q < 4; q++) {
            chh[q] = nh[q];
            cll[q] = nl[q];
        }
        if (ks < 15) {
            int off = (ks + 1) * 8;
            nh[0] = *(const float2*)(pAh + off);
            nh[1] = *(const float2*)(pAh + 8 * 128 + off);
            nh[2] = *(const float2*)(pAh + 16 * 128 + off);
            nh[3] = *(const float2*)(pAh + 24 * 128 + off);
            nl[0] = *(const float2*)(pAl + off);
            nl[1] = *(const float2*)(pAl + 8 * 128 + off);
            nl[2] = *(const float2*)(pAl + 16 * 128 + off);
            nl[3] = *(const float2*)(pAl + 24 * 128 + off);
        }
        uint32_t fah[2][4] = {
            {__float_as_uint(chh[0].x), __float_as_uint(chh[1].x),
             __float_as_uint(chh[0].y), __float_as_uint(chh[1].y)},
            {__float_as_uint(chh[2].x), __float_as_uint(chh[3].x),
             __float_as_uint(chh[2].y), __float_as_uint(chh[3].y)}};
        uint32_t fal[2][4] = {
            {__float_as_uint(cll[0].x), __float_as_uint(cll[1].x),
             __float_as_uint(cll[0].y), __float_as_uint(cll[1].y)},
            {__float_as_uint(cll[2].x), __float_as_uint(cll[3].x),
             __float_as_uint(cll[2].y), __float_as_uint(cll[3].y)}};

        int base = ((wn * 16 + ks) * 32 + lane) * STRD;
        float4 BH[NT / 2], BL[NT / 2];
#pragma unroll
        for (int q = 0; q < NT / 2; q++) {
            BH[q] = *(const float4*)(Wh + base + q * 4);
            BL[q] = *(const float4*)(Wl + base + q * 4);
        }
        const float* bhf = (const float*)BH;
        const float* blf = (const float*)BL;
#pragma unroll
        for (int nt = 0; nt < NT; nt++) {
            uint32_t bh0 = __float_as_uint(bhf[nt * 2]);
            uint32_t bh1 = __float_as_uint(bhf[nt * 2 + 1]);
            uint32_t bl0 = __float_as_uint(blf[nt * 2]);
            uint32_t bl1 = __float_as_uint(blf[nt * 2 + 1]);
#pragma unroll
            for (int t = 0; t < 2; t++) {
                mma8(c[t][nt], fah[t], bh0, bh1);   // hi*hi
                mma8(c[t][nt], fah[t], bl0, bl1);   // hi*lo
                mma8(c[t][nt], fal[t], bh0, bh1);   // lo*hi
            }
        }
    }

    // ---- epilogue: store H, fold attention dots ----
    float sa[4] = {0.f, 0.f, 0.f, 0.f};
    float sd[4] = {0.f, 0.f, 0.f, 0.f};
#pragma unroll
    for (int nt = 0; nt < NT; nt++) {
        int col0 = wn * (BN / 2) + nt * 8 + 2 * lk;
        float as0 = __ldg(a_s + col0), as1 = __ldg(a_s + col0 + 1);
        float ad0 = __ldg(a_d + col0), ad1 = __ldg(a_d + col0 + 1);
#pragma unroll
        for (int t = 0; t < 2; t++) {
            int rA = row0 + wm * 32 + t * 16 + lr;
            if (rA < M)
                *(float2*)(H + (size_t)rA * BN + col0) = make_float2(c[t][nt][0], c[t][nt][1]);
            if (rA + 8 < M)
                *(float2*)(H + (size_t)(rA + 8) * BN + col0) = make_float2(c[t][nt][2], c[t][nt][3]);
            sa[t * 2 + 0] += c[t][nt][0] * as0 + c[t][nt][1] * as1;
            sa[t * 2 + 1] += c[t][nt][2] * as0 + c[t][nt][3] * as1;
            sd[t * 2 + 0] += c[t][nt][0] * ad0 + c[t][nt][1] * ad1;
            sd[t * 2 + 1] += c[t][nt][2] * ad0 + c[t][nt][3] * ad1;
        }
    }
#pragma unroll
    for (int q = 0; q < 4; q++) {
        sa[q] += __shfl_xor_sync(0xffffffffu, sa[q], 1);
        sa[q] += __shfl_xor_sync(0xffffffffu, sa[q], 2);
        sd[q] += __shfl_xor_sync(0xffffffffu, sd[q], 1);
        sd[q] += __shfl_xor_sync(0xffffffffu, sd[q], 2);
    }
    if (lk == 0) {
#pragma unroll
        for (int t = 0; t < 2; t++) {
            int rl = wm * 32 + t * 16 + lr;
            atomicAdd(&s_sa[rl], sa[t * 2 + 0]);
            atomicAdd(&s_sd[rl], sd[t * 2 + 0]);
            atomicAdd(&s_sa[rl + 8], sa[t * 2 + 1]);
            atomicAdd(&s_sd[rl + 8], sd[t * 2 + 1]);
        }
    }
    __syncthreads();
    if (tid < 128) {
        int r = row0 + tid;
        if (r < M) {
            g_as[r] = s_sa[tid];
            g_ad[r] = s_sd[tid];
        }
    }
}

// ============ warp-per-dst-node segment softmax + weighted gather ============
// SPLIT: write tf32 hi/lo pair-permuted planes (feeds next GEMM) instead of fp32.

template <int D, bool SILU, bool SPLIT>
__global__ void k_agg(const float* __restrict__ h, const float* __restrict__ bias,
                      float* __restrict__ out, float* __restrict__ oh,
                      float* __restrict__ ol, int n) {
    constexpr int MAXDEG = 128;
    constexpr int FP = D / 32;  // floats per lane (4 or 2)
    __shared__ float wsh[8][MAXDEG];
    __shared__ int ssh[8][MAXDEG];
    int warp = threadIdx.x >> 5, lane = threadIdx.x & 31;
    int d = blockIdx.x * 8 + warp;
    if (d >= n) return;
    int st = g_start[d];
    int deg = g_deg[d] + 1;
    float ad = g_ad[d];
    int f = lane * FP;
    float acc[FP];
#pragma unroll
    for (int j = 0; j < FP; j++) acc[j] = 0.f;
    float inv;

    if (deg <= MAXDEG) {
        float m = -1e30f;
        for (int i = lane; i < deg; i += 32) {
            int s = g_csr[st + i];
            ssh[warp][i] = s;
            float al = g_as[s] + ad;
            al = al > 0.f ? al : NSLOPE * al;
            wsh[warp][i] = al;
            m = fmaxf(m, al);
        }
#pragma unroll
        for (int o = 16; o; o >>= 1) m = fmaxf(m, __shfl_xor_sync(0xffffffffu, m, o));
        __syncwarp();
        float den = 0.f;
        for (int i = lane; i < deg; i += 32) {
            float w = __expf(wsh[warp][i] - m);
            wsh[warp][i] = w;
            den += w;
        }
#pragma unroll
        for (int o = 16; o; o >>= 1) den += __shfl_xor_sync(0xffffffffu, den, o);
        __syncwarp();
        inv = 1.f / den;
        int i = 0;
        for (; i + 2 <= deg; i += 2) {
            int s0 = ssh[warp][i];
            int s1 = ssh[warp][i + 1];
            float c0 = wsh[warp][i];
            float c1 = wsh[warp][i + 1];
            const float* h0 = h + (size_t)s0 * D + f;
            const float* h1 = h + (size_t)s1 * D + f;
            if constexpr (FP == 4) {
                float4 v0 = *(const float4*)h0;
                float4 v1 = *(const float4*)h1;
                acc[0] += c0 * v0.x + c1 * v1.x;
                acc[1] += c0 * v0.y + c1 * v1.y;
                acc[2] += c0 * v0.z + c1 * v1.z;
                acc[3] += c0 * v0.w + c1 * v1.w;
            } else {
                float2 v0 = *(const float2*)h0;
                float2 v1 = *(const float2*)h1;
                acc[0] += c0 * v0.x + c1 * v1.x;
                acc[1] += c0 * v0.y + c1 * v1.y;
            }
        }
        if (i < deg) {
            int s0 = ssh[warp][i];
            float c0 = wsh[warp][i];
            const float* h0 = h + (size_t)s0 * D + f;
            if constexpr (FP == 4) {
                float4 v0 = *(const float4*)h0;
                acc[0] += c0 * v0.x;
                acc[1] += c0 * v0.y;
                acc[2] += c0 * v0.z;
                acc[3] += c0 * v0.w;
            } else {
                float2 v0 = *(const float2*)h0;
                acc[0] += c0 * v0.x;
                acc[1] += c0 * v0.y;
            }
        }
    } else {
        float m = -1e30f, den = 0.f;
        for (int i = 0; i < deg; i++) {
            int s = g_csr[st + i];
            float al = g_as[s] + ad;
            al = al > 0.f ? al : NSLOPE * al;
            float nm = fmaxf(m, al);
            float sc = __expf(m - nm);
            float w = __expf(al - nm);
            den = den * sc + w;
            const float* hp = h + (size_t)s * D + f;
#pragma unroll
            for (int j = 0; j < FP; j++) acc[j] = acc[j] * sc + w * hp[j];
            m = nm;
        }
        inv = 1.f / den;
    }

    float ov[FP];
#pragma unroll
    for (int j = 0; j < FP; j++) {
        float v = acc[j] * inv + bias[f + j];
        if (SILU) v = v / (1.f + __expf(-v));
        ov[j] = v;
    }

    if constexpr (SPLIT) {
        // write tf32 hi/lo pair-permuted planes: pairs (c, c+4), c in 0..3 mod 8
        float nv[FP];
#pragma unroll
        for (int j = 0; j < FP; j++) nv[j] = __shfl_down_sync(0xffffffffu, ov[j], 1);
        if ((lane & 1) == 0) {
            float o8[8] = {ov[0], nv[0], ov[1], nv[1], ov[2], nv[2], ov[3], nv[3]};
            float hi[8], lo[8];
#pragma unroll
            for (int j = 0; j < 8; j++) split2(o8[j], hi[j], lo[j]);
            size_t o = (size_t)d * 128 + (lane >> 1) * 8;
            *(float4*)(oh + o)     = make_float4(hi[0], hi[1], hi[2], hi[3]);
            *(float4*)(oh + o + 4) = make_float4(hi[4], hi[5], hi[6], hi[7]);
            *(float4*)(ol + o)     = make_float4(lo[0], lo[1], lo[2], lo[3]);
            *(float4*)(ol + o + 4) = make_float4(lo[4], lo[5], lo[6], lo[7]);
        }
    } else {
#pragma unroll
        for (int j = 0; j < FP; j++) out[(size_t)d * D + f + j] = ov[j];
    }
}

// ========================== log_softmax over 64 cols ==========================

__global__ void k_lsm(const float* __restrict__ in, float* __restrict__ out, int n) {
    int warp = threadIdx.x >> 5, lane = threadIdx.x & 31;
    int r = blockIdx.x * 8 + warp;
    if (r >= n) return;
    float2 v = *(const float2*)&in[(size_t)r * 64 + lane * 2];
    float m = fmaxf(v.x, v.y);
#pragma unroll
    for (int o = 16; o; o >>= 1) m = fmaxf(m, __shfl_xor_sync(0xffffffffu, m, o));
    float s = __expf(v.x - m) + __expf(v.y - m);
#pragma unroll
    for (int o = 16; o; o >>= 1) s += __shfl_xor_sync(0xffffffffu, s, o);
    float l = m + __logf(s);
    float2 o2 = make_float2(v.x - l, v.y - l);
    *(float2*)&out[(size_t)r * 64 + lane * 2] = o2;
}

// ========================== host launcher ==========================

extern "C" void kernel_launch(void* const* d_in, const int* in_sizes, int n_in,
                              void* d_out, int out_size) {
    const float* x   = (const float*)d_in[0];
    const int*   ei  = (const int*)d_in[1];
    const float* W0  = (const float*)d_in[2];
    const float* as0 = (const float*)d_in[3];
    const float* ad0 = (const float*)d_in[4];
    const float* b0  = (const float*)d_in[5];
    const float* W1  = (const float*)d_in[6];
    const float* as1 = (const float*)d_in[7];
    const float* ad1 = (const float*)d_in[8];
    const float* b1  = (const float*)d_in[9];
    const float* W2  = (const float*)d_in[10];
    const float* as2 = (const float*)d_in[11];
    const float* ad2 = (const float*)d_in[12];
    const float* b2  = (const float*)d_in[13];

    int n = in_sizes[0] / 128;  // 50000
    int e = in_sizes[1] / 2;    // 600000
    const int* src = ei;
    const int* dst = ei + e;
    float* outp = (float*)d_out;

    float *ph, *pah, *pal, *po2;
    cudaGetSymbolAddress((void**)&ph, g_h);
    cudaGetSymbolAddress((void**)&pah, g_ah);
    cudaGetSymbolAddress((void**)&pal, g_al);
    cudaGetSymbolAddress((void**)&po2, g_o2);

    const int SM128 = 2 * (2 * 16 * 32 * 20) * 4;  // 163840 B
    const int SM64  = 2 * (2 * 16 * 32 * 12) * 4;  // 98304 B
    cudaFuncSetAttribute(k_tc<128>, cudaFuncAttributeMaxDynamicSharedMemorySize, SM128);
    cudaFuncSetAttribute(k_tc<64>,  cudaFuncAttributeMaxDynamicSharedMemorySize, SM64);

    int nbN = (n + 255) / 256;
    int nbE = (e + 255) / 256;
    int nbC = (n * 16 + 255) / 256;
    int nbG = (n + 127) / 128;
    int nbA = (n + 7) / 8;
    int nbW = (n + 7) / 8;

    // order chosen so the 4th launch (ncu capture slot) is k_tc<128>
    k_cvt<<<nbC, 256>>>(x, pah, pal, n);
    k_zero<<<nbN, 256>>>(n);
    k_count<<<nbE, 256>>>(dst, e);
    k_tc<128><<<nbG, 256, SM128>>>(pah, pal, W0, ph, as0, ad0, n);   // layer 0 GEMM
    k_alloc<<<nbN, 256>>>(n);
    k_scatter<<<nbE, 256>>>(src, dst, e);

    // layer 0 agg (SiLU, split-output feeds layer-1 GEMM)
    k_agg<128, true, true><<<nbA, 256>>>(ph, b0, nullptr, pah, pal, n);

    // layer 1
    k_tc<128><<<nbG, 256, SM128>>>(pah, pal, W1, ph, as1, ad1, n);
    k_agg<128, true, true><<<nbA, 256>>>(ph, b1, nullptr, pah, pal, n);

    // layer 2: 128 -> 64, plain fp32 out, then log_softmax
    k_tc<64><<<nbG, 256, SM64>>>(pah, pal, W2, ph, as2, ad2, n);
    k_agg<64, false, false><<<nbA, 256>>>(ph, b2, po2, nullptr, nullptr, n);
    k_lsm<<<nbW, 256>>>(po2, outp, n);
}

// round 16
// speedup vs baseline: 1.3179x; 1.3179x over previous
#include <cuda_runtime.h>
#include <cstdint>

#define NSLOPE 0.2f
#define NMAX   50048
#define EMAX   655360

// ---- device scratch (no runtime allocation allowed) ----
__device__ float g_h[NMAX * 128];     // h = in @ W (fp32)
__device__ float g_ahp[NMAX * 128];   // A hi tf32 plane (pair-permuted)
__device__ float g_alp[NMAX * 128];   // A lo tf32 plane (pair-permuted)
__device__ float g_wh[40960];         // W hi planes, all 3 layers (pair-permuted)
__device__ float g_wl[40960];         // W lo planes
__device__ float g_o2[NMAX * 64];     // final pre-log-softmax
__device__ float g_as[NMAX];          // h . a_src per node
__device__ float g_ad[NMAX];          // h . a_dst per node
__device__ int   g_deg[NMAX];         // in-degree (w/o self loop)
__device__ int   g_start[NMAX];       // CSR segment start (by dst)
__device__ int   g_cur[NMAX];         // scatter cursors
__device__ int   g_csr[EMAX];         // src node per CSR slot
__device__ int   g_cnt;               // global slot allocator

#define TF32_RND(u, f) asm("cvt.rna.tf32.f32 %0, %1;" : "=r"(u) : "f"(f))

__device__ __forceinline__ void split2(float v, float& hi, float& lo) {
    uint32_t hb;
    TF32_RND(hb, v);
    hi = __uint_as_float(hb);
    uint32_t lb;
    TF32_RND(lb, v - hi);
    lo = __uint_as_float(lb);
}

// m16n8k8 tf32 HMMA, C += A*B (row.col)
__device__ __forceinline__ void mma8(float* c, const uint32_t* a, uint32_t b0, uint32_t b1) {
    asm volatile(
        "mma.sync.aligned.m16n8k8.row.col.f32.tf32.tf32.f32 "
        "{%0,%1,%2,%3}, {%4,%5,%6,%7}, {%8,%9}, {%0,%1,%2,%3};"
        : "+f"(c[0]), "+f"(c[1]), "+f"(c[2]), "+f"(c[3])
        : "r"(a[0]), "r"(a[1]), "r"(a[2]), "r"(a[3]), "r"(b0), "r"(b1));
}

// ============== x -> pair-permuted tf32 hi/lo planes ==============
// A slot(col c) = (c>>3)*8 + (c&3)*2 + ((c>>2)&1): pairs (c, c+4) adjacent.

__global__ void k_cvt(const float* __restrict__ x, float* __restrict__ ah,
                      float* __restrict__ al, int n) {
    int i = blockIdx.x * 256 + threadIdx.x;
    if (i >= n * 16) return;
    int r = i >> 4, g = i & 15;
    const float* xp = x + (size_t)r * 128 + g * 8;
    float4 v0 = *(const float4*)xp;
    float4 v1 = *(const float4*)(xp + 4);
    float vv[8] = {v0.x, v0.y, v0.z, v0.w, v1.x, v1.y, v1.z, v1.w};
    float hi[8], lo[8];
#pragma unroll
    for (int j = 0; j < 8; j++) split2(vv[j], hi[j], lo[j]);
    size_t o = (size_t)r * 128 + g * 8;
    *(float4*)(ah + o)     = make_float4(hi[0], hi[4], hi[1], hi[5]);
    *(float4*)(ah + o + 4) = make_float4(hi[2], hi[6], hi[3], hi[7]);
    *(float4*)(al + o)     = make_float4(lo[0], lo[4], lo[1], lo[5]);
    *(float4*)(al + o + 4) = make_float4(lo[2], lo[6], lo[3], lo[7]);
}

// ============== W -> pair-permuted tf32 hi/lo planes ==============
// element (k, col) -> ((ks*4+lk)*BN + col)*2 + u, k = ks*8+lk+4u.

__global__ void k_wcvt(const float* __restrict__ W, float* __restrict__ wh,
                       float* __restrict__ wl, int BN) {
    int i = blockIdx.x * 256 + threadIdx.x;
    if (i >= 128 * BN) return;
    int k = i / BN, col = i % BN;
    int ks = k >> 3, r = k & 7;
    int lk = r & 3, u = r >> 2;
    float hi, lo;
    split2(W[i], hi, lo);
    int o = ((ks * 4 + lk) * BN + col) * 2 + u;
    wh[o] = hi;
    wl[o] = lo;
}

// ========================== CSR build ==========================

__global__ void k_zero(int n) {
    int i = blockIdx.x * 256 + threadIdx.x;
    if (i < n) g_deg[i] = 0;
    if (i == 0) g_cnt = 0;
}

__global__ void k_count(const int* __restrict__ dst, int e) {
    int i = blockIdx.x * 256 + threadIdx.x;
    if (i < e) atomicAdd(&g_deg[dst[i]], 1);
}

__global__ void k_alloc(int n) {
    __shared__ int s[256];
    __shared__ int base;
    int tid = threadIdx.x;
    int i = blockIdx.x * 256 + tid;
    int deg = (i < n) ? g_deg[i] + 1 : 0;  // +1 self loop
    s[tid] = deg;
    __syncthreads();
    for (int off = 1; off < 256; off <<= 1) {
        int a = s[tid];
        int b = (tid >= off) ? s[tid - off] : 0;
        __syncthreads();
        s[tid] = a + b;
        __syncthreads();
    }
    if (tid == 255) base = atomicAdd(&g_cnt, s[255]);
    __syncthreads();
    if (i < n) {
        int st = base + s[tid] - deg;
        g_start[i] = st;
        g_csr[st] = i;   // self-loop occupies slot 0
        g_cur[i] = 1;
    }
}

__global__ void k_scatter(const int* __restrict__ src, const int* __restrict__ dst, int e) {
    int i = blockIdx.x * 256 + threadIdx.x;
    if (i < e) {
        int d = dst[i];
        int p = atomicAdd(&g_cur[d], 1);
        g_csr[g_start[d] + p] = src[i];
    }
}

// ============ mma.sync 3xTF32 GEMM, occupancy-first ============
// H[M,BN] = A[M,128] @ W[128,BN]. Tile 64 x BN, 256 thr = 8 warps (2 wm x 4 wn).
// K chunked by 32 through XOR-swizzled smem (pure copies of pre-split planes).
// All fragment loads are half-warp-conflict-free LDS.64. 3 CTAs/SM.

template <int BN>
__global__ __launch_bounds__(256, 3) void k_tc(
    const float* __restrict__ Ah, const float* __restrict__ Al,
    const float* __restrict__ Wh, const float* __restrict__ Wl,
    float* __restrict__ H, const float* __restrict__ a_s,
    const float* __restrict__ a_d, int M)
{
    constexpr int NT  = BN / 32;        // N-tiles per warp (4 or 2)
    constexpr int ASZ = 64 * 32;        // A chunk floats per plane
    constexpr int BSZ = 32 * BN;        // B chunk floats per plane

    extern __shared__ float sm[];
    float* As[2] = {sm, sm + ASZ};                      // hi, lo
    float* Bs[2] = {sm + 2 * ASZ, sm + 2 * ASZ + BSZ};  // hi, lo
    __shared__ float s_sa[64], s_sd[64];

    int tid = threadIdx.x, wid = tid >> 5, lane = tid & 31;
    int wm = wid >> 2, wn = wid & 3;
    int lr = lane >> 2, lk = lane & 3;
    int row0 = blockIdx.x * 64;

    if (tid < 64) {
        s_sa[tid] = 0.f;
        s_sd[tid] = 0.f;
    }

    float c[2][NT][4];
#pragma unroll
    for (int t = 0; t < 2; t++)
#pragma unroll
        for (int nt = 0; nt < NT; nt++)
#pragma unroll
            for (int q = 0; q < 4; q++) c[t][nt][q] = 0.f;

    // staging indices (hoisted)
    int ar = tid >> 2;                 // A: row 0..63
    int as0 = (tid & 3) * 8;           // A: slot base
    int am = (ar & 3) * 8;             // A: xor mask
    const float* gA[2] = {Ah + (size_t)(row0 + ar) * 128, Al + (size_t)(row0 + ar) * 128};
    int bt = (BN == 128) ? 16 : 8;     // B floats per thread
    int bprow = tid / 16;              // B: pairslot row 0..15
    int bc2 = (tid % 16) * bt;         // B: col2 base
    int bxm = (bprow & 3) * 8;         // B: xor mask

    for (int cc = 0; cc < 4; cc++) {
        // ---- stage A chunk (both planes): 64 rows x 32 slots ----
#pragma unroll
        for (int pl = 0; pl < 2; pl++) {
            float4 v0 = *(const float4*)(gA[pl] + cc * 32 + as0);
            float4 v1 = *(const float4*)(gA[pl] + cc * 32 + as0 + 4);
            *(float4*)(As[pl] + ar * 32 + (as0 ^ am))       = v0;
            *(float4*)(As[pl] + ar * 32 + ((as0 + 4) ^ am)) = v1;
        }
        // ---- stage B chunk (both planes): 16 pairslots x 2BN ----
#pragma unroll
        for (int pl = 0; pl < 2; pl++) {
            const float* gw = (pl == 0 ? Wh : Wl) + cc * 32 * BN;
#pragma unroll
            for (int q = 0; q < (BN == 128 ? 4 : 2); q++) {
                int c2 = bc2 + q * 4;
                float4 v = *(const float4*)(gw + bprow * 2 * BN + c2);
                *(float4*)(Bs[pl] + bprow * 2 * BN + (c2 ^ bxm)) = v;
            }
        }
        __syncthreads();

#pragma unroll
        for (int ks = 0; ks < 4; ks++) {
            // A fragments
            uint32_t fa[2][2][4];  // [plane][t][4]
#pragma unroll
            for (int t = 0; t < 2; t++) {
                int r0 = wm * 32 + t * 16 + lr;
                int r1 = r0 + 8;
#pragma unroll
                for (int pl = 0; pl < 2; pl++) {
                    float2 f0 = *(const float2*)(As[pl] + r0 * 32 + ((ks * 8 + lk * 2) ^ ((r0 & 3) * 8)));
                    float2 f1 = *(const float2*)(As[pl] + r1 * 32 + ((ks * 8 + lk * 2) ^ ((r1 & 3) * 8)));
                    fa[pl][t][0] = __float_as_uint(f0.x);
                    fa[pl][t][1] = __float_as_uint(f1.x);
                    fa[pl][t][2] = __float_as_uint(f0.y);
                    fa[pl][t][3] = __float_as_uint(f1.y);
                }
            }
            // B fragments + MMA
            int prow = ks * 4 + lk;
#pragma unroll
            for (int nt = 0; nt < NT; nt++) {
                int col = wn * (BN / 4) + nt * 8 + lr;
                float2 bh = *(const float2*)(Bs[0] + prow * 2 * BN + ((2 * col) ^ (lk * 8)));
                float2 bl = *(const float2*)(Bs[1] + prow * 2 * BN + ((2 * col) ^ (lk * 8)));
                uint32_t bh0 = __float_as_uint(bh.x), bh1 = __float_as_uint(bh.y);
                uint32_t bl0 = __float_as_uint(bl.x), bl1 = __float_as_uint(bl.y);
#pragma unroll
                for (int t = 0; t < 2; t++) {
                    mma8(c[t][nt], fa[0][t], bh0, bh1);   // hi*hi
                    mma8(c[t][nt], fa[0][t], bl0, bl1);   // hi*lo
                    mma8(c[t][nt], fa[1][t], bh0, bh1);   // lo*hi
                }
            }
        }
        __syncthreads();
    }

    // ---- epilogue: store H, fold attention dots ----
    float sa[4] = {0.f, 0.f, 0.f, 0.f};
    float sd[4] = {0.f, 0.f, 0.f, 0.f};
#pragma unroll
    for (int nt = 0; nt < NT; nt++) {
        int col0 = wn * (BN / 4) + nt * 8 + 2 * lk;
        float as_ = __ldg(a_s + col0), as1 = __ldg(a_s + col0 + 1);
        float ad_ = __ldg(a_d + col0), ad1 = __ldg(a_d + col0 + 1);
#pragma unroll
        for (int t = 0; t < 2; t++) {
            int rA = row0 + wm * 32 + t * 16 + lr;
            if (rA < M)
                *(float2*)(H + (size_t)rA * BN + col0) = make_float2(c[t][nt][0], c[t][nt][1]);
            if (rA + 8 < M)
                *(float2*)(H + (size_t)(rA + 8) * BN + col0) = make_float2(c[t][nt][2], c[t][nt][3]);
            sa[t * 2 + 0] += c[t][nt][0] * as_ + c[t][nt][1] * as1;
            sa[t * 2 + 1] += c[t][nt][2] * as_ + c[t][nt][3] * as1;
            sd[t * 2 + 0] += c[t][nt][0] * ad_ + c[t][nt][1] * ad1;
            sd[t * 2 + 1] += c[t][nt][2] * ad_ + c[t][nt][3] * ad1;
        }
    }
#pragma unroll
    for (int q = 0; q < 4; q++) {
        sa[q] += __shfl_xor_sync(0xffffffffu, sa[q], 1);
        sa[q] += __shfl_xor_sync(0xffffffffu, sa[q], 2);
        sd[q] += __shfl_xor_sync(0xffffffffu, sd[q], 1);
        sd[q] += __shfl_xor_sync(0xffffffffu, sd[q], 2);
    }
    if (lk == 0) {
#pragma unroll
        for (int t = 0; t < 2; t++) {
            int rl = wm * 32 + t * 16 + lr;
            atomicAdd(&s_sa[rl], sa[t * 2 + 0]);
            atomicAdd(&s_sd[rl], sd[t * 2 + 0]);
            atomicAdd(&s_sa[rl + 8], sa[t * 2 + 1]);
            atomicAdd(&s_sd[rl + 8], sd[t * 2 + 1]);
        }
    }
    __syncthreads();
    if (tid < 64) {
        int r = row0 + tid;
        if (r < M) {
            g_as[r] = s_sa[tid];
            g_ad[r] = s_sd[tid];
        }
    }
}

// ============ warp-per-dst-node segment softmax + weighted gather ============
// SPLIT: write tf32 hi/lo pair-permuted planes (feeds next GEMM) instead of fp32.

template <int D, bool SILU, bool SPLIT>
__global__ void k_agg(const float* __restrict__ h, const float* __restrict__ bias,
                      float* __restrict__ out, float* __restrict__ oh,
                      float* __restrict__ ol, int n) {
    constexpr int MAXDEG = 128;
    constexpr int FP = D / 32;  // floats per lane (4 or 2)
    __shared__ float wsh[8][MAXDEG];
    __shared__ int ssh[8][MAXDEG];
    int warp = threadIdx.x >> 5, lane = threadIdx.x & 31;
    int d = blockIdx.x * 8 + warp;
    if (d >= n) return;
    int st = g_start[d];
    int deg = g_deg[d] + 1;
    float ad = g_ad[d];
    int f = lane * FP;
    float acc[FP];
#pragma unroll
    for (int j = 0; j < FP; j++) acc[j] = 0.f;
    float inv;

    if (deg <= MAXDEG) {
        float m = -1e30f;
        for (int i = lane; i < deg; i += 32) {
            int s = g_csr[st + i];
            ssh[warp][i] = s;
            float al = g_as[s] + ad;
            al = al > 0.f ? al : NSLOPE * al;
            wsh[warp][i] = al;
            m = fmaxf(m, al);
        }
#pragma unroll
        for (int o = 16; o; o >>= 1) m = fmaxf(m, __shfl_xor_sync(0xffffffffu, m, o));
        __syncwarp();
        float den = 0.f;
        for (int i = lane; i < deg; i += 32) {
            float w = __expf(wsh[warp][i] - m);
            wsh[warp][i] = w;
            den += w;
        }
#pragma unroll
        for (int o = 16; o; o >>= 1) den += __shfl_xor_sync(0xffffffffu, den, o);
        __syncwarp();
        inv = 1.f / den;
        int i = 0;
        for (; i + 2 <= deg; i += 2) {
            int s0 = ssh[warp][i];
            int s1 = ssh[warp][i + 1];
            float c0 = wsh[warp][i];
            float c1 = wsh[warp][i + 1];
            const float* h0 = h + (size_t)s0 * D + f;
            const float* h1 = h + (size_t)s1 * D + f;
            if constexpr (FP == 4) {
                float4 v0 = *(const float4*)h0;
                float4 v1 = *(const float4*)h1;
                acc[0] += c0 * v0.x + c1 * v1.x;
                acc[1] += c0 * v0.y + c1 * v1.y;
                acc[2] += c0 * v0.z + c1 * v1.z;
                acc[3] += c0 * v0.w + c1 * v1.w;
            } else {
                float2 v0 = *(const float2*)h0;
                float2 v1 = *(const float2*)h1;
                acc[0] += c0 * v0.x + c1 * v1.x;
                acc[1] += c0 * v0.y + c1 * v1.y;
            }
        }
        if (i < deg) {
            int s0 = ssh[warp][i];
            float c0 = wsh[warp][i];
            const float* h0 = h + (size_t)s0 * D + f;
            if constexpr (FP == 4) {
                float4 v0 = *(const float4*)h0;
                acc[0] += c0 * v0.x;
                acc[1] += c0 * v0.y;
                acc[2] += c0 * v0.z;
                acc[3] += c0 * v0.w;
            } else {
                float2 v0 = *(const float2*)h0;
                acc[0] += c0 * v0.x;
                acc[1] += c0 * v0.y;
            }
        }
    } else {
        float m = -1e30f, den = 0.f;
        for (int i = 0; i < deg; i++) {
            int s = g_csr[st + i];
            float al = g_as[s] + ad;
            al = al > 0.f ? al : NSLOPE * al;
            float nm = fmaxf(m, al);
            float sc = __expf(m - nm);
            float w = __expf(al - nm);
            den = den * sc + w;
            const float* hp = h + (size_t)s * D + f;
#pragma unroll
            for (int j = 0; j < FP; j++) acc[j] = acc[j] * sc + w * hp[j];
            m = nm;
        }
        inv = 1.f / den;
    }

    float ov[FP];
#pragma unroll
    for (int j = 0; j < FP; j++) {
        float v = acc[j] * inv + bias[f + j];
        if (SILU) v = v / (1.f + __expf(-v));
        ov[j] = v;
    }

    if constexpr (SPLIT) {
        // write tf32 hi/lo pair-permuted planes: pairs (c, c+4) adjacent
        float nv[FP];
#pragma unroll
        for (int j = 0; j < FP; j++) nv[j] = __shfl_down_sync(0xffffffffu, ov[j], 1);
        if ((lane & 1) == 0) {
            float o8[8] = {ov[0], nv[0], ov[1], nv[1], ov[2], nv[2], ov[3], nv[3]};
            float hi[8], lo[8];
#pragma unroll
            for (int j = 0; j < 8; j++) split2(o8[j], hi[j], lo[j]);
            size_t o = (size_t)d * 128 + (lane >> 1) * 8;
            *(float4*)(oh + o)     = make_float4(hi[0], hi[1], hi[2], hi[3]);
            *(float4*)(oh + o + 4) = make_float4(hi[4], hi[5], hi[6], hi[7]);
            *(float4*)(ol + o)     = make_float4(lo[0], lo[1], lo[2], lo[3]);
            *(float4*)(ol + o + 4) = make_float4(lo[4], lo[5], lo[6], lo[7]);
        }
    } else {
#pragma unroll
        for (int j = 0; j < FP; j++) out[(size_t)d * D + f + j] = ov[j];
    }
}

// ========================== log_softmax over 64 cols ==========================

__global__ void k_lsm(const float* __restrict__ in, float* __restrict__ out, int n) {
    int warp = threadIdx.x >> 5, lane = threadIdx.x & 31;
    int r = blockIdx.x * 8 + warp;
    if (r >= n) return;
    float2 v = *(const float2*)&in[(size_t)r * 64 + lane * 2];
    float m = fmaxf(v.x, v.y);
#pragma unroll
    for (int o = 16; o; o >>= 1) m = fmaxf(m, __shfl_xor_sync(0xffffffffu, m, o));
    float s = __expf(v.x - m) + __expf(v.y - m);
#pragma unroll
    for (int o = 16; o; o >>= 1) s += __shfl_xor_sync(0xffffffffu, s, o);
    float l = m + __logf(s);
    float2 o2 = make_float2(v.x - l, v.y - l);
    *(float2*)&out[(size_t)r * 64 + lane * 2] = o2;
}

// ========================== host launcher ==========================

extern "C" void kernel_launch(void* const* d_in, const int* in_sizes, int n_in,
                              void* d_out, int out_size) {
    const float* x   = (const float*)d_in[0];
    const int*   ei  = (const int*)d_in[1];
    const float* W0  = (const float*)d_in[2];
    const float* as0 = (const float*)d_in[3];
    const float* ad0 = (const float*)d_in[4];
    const float* b0  = (const float*)d_in[5];
    const float* W1  = (const float*)d_in[6];
    const float* as1 = (const float*)d_in[7];
    const float* ad1 = (const float*)d_in[8];
    const float* b1  = (const float*)d_in[9];
    const float* W2  = (const float*)d_in[10];
    const float* as2 = (const float*)d_in[11];
    const float* ad2 = (const float*)d_in[12];
    const float* b2  = (const float*)d_in[13];

    int n = in_sizes[0] / 128;  // 50000
    int e = in_sizes[1] / 2;    // 600000
    const int* src = ei;
    const int* dst = ei + e;
    float* outp = (float*)d_out;

    float *ph, *pah, *pal, *pwh, *pwl, *po2;
    cudaGetSymbolAddress((void**)&ph, g_h);
    cudaGetSymbolAddress((void**)&pah, g_ahp);
    cudaGetSymbolAddress((void**)&pal, g_alp);
    cudaGetSymbolAddress((void**)&pwh, g_wh);
    cudaGetSymbolAddress((void**)&pwl, g_wl);
    cudaGetSymbolAddress((void**)&po2, g_o2);

    const int SM128 = (2 * 64 * 32 + 2 * 32 * 128) * 4;  // 49152 B
    const int SM64  = (2 * 64 * 32 + 2 * 32 * 64) * 4;   // 32768 B
    cudaFuncSetAttribute(k_tc<128>, cudaFuncAttributeMaxDynamicSharedMemorySize, SM128);
    cudaFuncSetAttribute(k_tc<64>,  cudaFuncAttributeMaxDynamicSharedMemorySize, SM64);

    int nbN = (n + 255) / 256;
    int nbE = (e + 255) / 256;
    int nbC = (n * 16 + 255) / 256;
    int nbW128 = (128 * 128 + 255) / 256;
    int nbW64  = (128 * 64 + 255) / 256;
    int nbG = (n + 63) / 64;
    int nbA = (n + 7) / 8;
    int nbL = (n + 7) / 8;

    // launch order keeps k_tc<128> in the ncu capture slot
    k_cvt<<<nbC, 256>>>(x, pah, pal, n);
    k_wcvt<<<nbW128, 256>>>(W0, pwh, pwl, 128);
    k_zero<<<nbN, 256>>>(n);
    k_tc<128><<<nbG, 256, SM128>>>(pah, pal, pwh, pwl, ph, as0, ad0, n);  // layer 0
    k_count<<<nbE, 256>>>(dst, e);
    k_alloc<<<nbN, 256>>>(n);
    k_scatter<<<nbE, 256>>>(src, dst, e);
    k_wcvt<<<nbW128, 256>>>(W1, pwh + 16384, pwl + 16384, 128);
    k_agg<128, true, true><<<nbA, 256>>>(ph, b0, nullptr, pah, pal, n);

    // layer 1
    k_tc<128><<<nbG, 256, SM128>>>(pah, pal, pwh + 16384, pwl + 16384, ph, as1, ad1, n);
    k_wcvt<<<nbW64, 256>>>(W2, pwh + 32768, pwl + 32768, 64);
    k_agg<128, true, true><<<nbA, 256>>>(ph, b1, nullptr, pah, pal, n);

    // layer 2: 128 -> 64
    k_tc<64><<<nbG, 256, SM64>>>(pah, pal, pwh + 32768, pwl + 32768, ph, as2, ad2, n);
    k_agg<64, false, false><<<nbA, 256>>>(ph, b2, po2, nullptr, nullptr, n);
    k_lsm<<<nbL, 256>>>(po2, outp, n);
}

// round 17
// speedup vs baseline: 1.5855x; 1.2031x over previous
#include <cuda_runtime.h>
#include <cstdint>

#define NSLOPE 0.2f
#define NMAX   50048
#define EMAX   655360

// ---- device scratch (no runtime allocation allowed) ----
__device__ float g_h[NMAX * 128];     // h = in @ W (fp32)
__device__ float g_ahp[NMAX * 128];   // A hi tf32 plane (fragment-major)
__device__ float g_alp[NMAX * 128];   // A lo tf32 plane (fragment-major)
__device__ float g_wh[40960];         // W hi planes, 3 layers (fragment-major)
__device__ float g_wl[40960];         // W lo planes
__device__ float g_o2[NMAX * 64];     // final pre-log-softmax
__device__ float g_as[NMAX];          // h . a_src per node
__device__ float g_ad[NMAX];          // h . a_dst per node
__device__ int   g_deg[NMAX];         // in-degree (w/o self loop)
__device__ int   g_start[NMAX];       // CSR segment start (by dst)
__device__ int   g_cur[NMAX];         // scatter cursors
__device__ int   g_csr[EMAX];         // src node per CSR slot
__device__ int   g_cnt;               // global slot allocator

#define TF32_RND(u, f) asm("cvt.rna.tf32.f32 %0, %1;" : "=r"(u) : "f"(f))

__device__ __forceinline__ void split2(float v, float& hi, float& lo) {
    uint32_t hb;
    TF32_RND(hb, v);
    hi = __uint_as_float(hb);
    uint32_t lb;
    TF32_RND(lb, v - hi);
    lo = __uint_as_float(lb);
}

// m16n8k8 tf32 HMMA, C += A*B (row.col)
__device__ __forceinline__ void mma8(float* c, const uint32_t* a, uint32_t b0, uint32_t b1) {
    asm volatile(
        "mma.sync.aligned.m16n8k8.row.col.f32.tf32.tf32.f32 "
        "{%0,%1,%2,%3}, {%4,%5,%6,%7}, {%8,%9}, {%0,%1,%2,%3};"
        : "+f"(c[0]), "+f"(c[1]), "+f"(c[2]), "+f"(c[3])
        : "r"(a[0]), "r"(a[1]), "r"(a[2]), "r"(a[3]), "r"(b0), "r"(b1));
}

// Fragment-major A layout: block (row>>3, g=c>>3) of 64 floats, lane-ordered:
//   off = ((row>>3)*16 + g)*64 + (row&7)*8 + (c&3)*2 + ((c>>2)&1)
// One warp's fragment load = contiguous 256B LDG.64.

// ============== x -> fragment-major tf32 hi/lo planes ==============

__global__ void k_cvt(const float* __restrict__ x, float* __restrict__ ah,
                      float* __restrict__ al, int n) {
    int i = blockIdx.x * 256 + threadIdx.x;
    if (i >= n * 16) return;
    int r = i >> 4, g = i & 15;
    const float* xp = x + (size_t)r * 128 + g * 8;
    float4 v0 = *(const float4*)xp;
    float4 v1 = *(const float4*)(xp + 4);
    float vv[8] = {v0.x, v0.y, v0.z, v0.w, v1.x, v1.y, v1.z, v1.w};
    float hi[8], lo[8];
#pragma unroll
    for (int j = 0; j < 8; j++) split2(vv[j], hi[j], lo[j]);
    size_t o = ((size_t)(r >> 3) * 16 + g) * 64 + (r & 7) * 8;
    *(float4*)(ah + o)     = make_float4(hi[0], hi[4], hi[1], hi[5]);
    *(float4*)(ah + o + 4) = make_float4(hi[2], hi[6], hi[3], hi[7]);
    *(float4*)(al + o)     = make_float4(lo[0], lo[4], lo[1], lo[5]);
    *(float4*)(al + o + 4) = make_float4(lo[2], lo[6], lo[3], lo[7]);
}

// ============== W -> fragment-major tf32 hi/lo planes ==============
// element (k, col): ks=k>>3, lk=(k&7)&3, u=(k&7)>>2
//   off = ((col>>3)*16 + ks)*64 + (col&7)*8 + lk*2 + u

__global__ void k_wcvt(const float* __restrict__ W, float* __restrict__ wh,
                       float* __restrict__ wl, int BN) {
    int i = blockIdx.x * 256 + threadIdx.x;
    if (i >= 128 * BN) return;
    int k = i / BN, col = i % BN;
    int ks = k >> 3, r = k & 7;
    int lk = r & 3, u = r >> 2;
    float hi, lo;
    split2(W[i], hi, lo);
    int o = ((col >> 3) * 16 + ks) * 64 + (col & 7) * 8 + lk * 2 + u;
    wh[o] = hi;
    wl[o] = lo;
}

// ========================== CSR build ==========================

__global__ void k_zero(int n) {
    int i = blockIdx.x * 256 + threadIdx.x;
    if (i < n) g_deg[i] = 0;
    if (i == 0) g_cnt = 0;
}

__global__ void k_count(const int* __restrict__ dst, int e) {
    int i = blockIdx.x * 256 + threadIdx.x;
    if (i < e) atomicAdd(&g_deg[dst[i]], 1);
}

__global__ void k_alloc(int n) {
    __shared__ int s[256];
    __shared__ int base;
    int tid = threadIdx.x;
    int i = blockIdx.x * 256 + tid;
    int deg = (i < n) ? g_deg[i] + 1 : 0;  // +1 self loop
    s[tid] = deg;
    __syncthreads();
    for (int off = 1; off < 256; off <<= 1) {
        int a = s[tid];
        int b = (tid >= off) ? s[tid - off] : 0;
        __syncthreads();
        s[tid] = a + b;
        __syncthreads();
    }
    if (tid == 255) base = atomicAdd(&g_cnt, s[255]);
    __syncthreads();
    if (i < n) {
        int st = base + s[tid] - deg;
        g_start[i] = st;
        g_csr[st] = i;   // self-loop occupies slot 0
        g_cur[i] = 1;
    }
}

__global__ void k_scatter(const int* __restrict__ src, const int* __restrict__ dst, int e) {
    int i = blockIdx.x * 256 + threadIdx.x;
    if (i < e) {
        int d = dst[i];
        int p = atomicAdd(&g_cur[d], 1);
        g_csr[g_start[d] + p] = src[i];
    }
}

// ============ mma.sync 3xTF32 GEMM, smem-free data path ============
// H[M,BN] = A[M,128] @ W[128,BN]. Tile 64 x BN, 256 thr = 8 warps (2 wm x 4 wn).
// Both operands fragment-major in gmem: every fragment = one coalesced 256B
// LDG.64 per warp. No staging smem, no mainloop barriers.

template <int BN>
__global__ __launch_bounds__(256, 2) void k_tc(
    const float* __restrict__ Ah, const float* __restrict__ Al,
    const float* __restrict__ Wh, const float* __restrict__ Wl,
    float* __restrict__ H, const float* __restrict__ a_s,
    const float* __restrict__ a_d, int M)
{
    constexpr int NT = BN / 32;   // N-tiles per warp (4 or 2)

    __shared__ float s_sa[64], s_sd[64];

    int tid = threadIdx.x, wid = tid >> 5, lane = tid & 31;
    int wm = wid >> 2, wn = wid & 3;
    int lr = lane >> 2, lk = lane & 3;
    int row0 = blockIdx.x * 64;

    if (tid < 64) {
        s_sa[tid] = 0.f;
        s_sd[tid] = 0.f;
    }

    float c[2][NT][4];
#pragma unroll
    for (int t = 0; t < 2; t++)
#pragma unroll
        for (int nt = 0; nt < NT; nt++)
#pragma unroll
            for (int q = 0; q < 4; q++) c[t][nt][q] = 0.f;

    // hoisted fragment base offsets (advance by 64 per ks)
    int lo_ = lr * 8 + lk * 2;
    size_t aoff[2][2];   // [t][half]
#pragma unroll
    for (int t = 0; t < 2; t++)
#pragma unroll
        for (int h = 0; h < 2; h++)
            aoff[t][h] = ((size_t)((row0 >> 3) + wm * 4 + t * 2 + h) * 16) * 64 + lo_;
    size_t boff[NT];
#pragma unroll
    for (int nt = 0; nt < NT; nt++)
        boff[nt] = ((size_t)(wn * NT + nt) * 16) * 64 + lo_;

#pragma unroll
    for (int ks = 0; ks < 16; ks++) {
        float2 a_[2][2][2];  // [plane][t][half]
#pragma unroll
        for (int t = 0; t < 2; t++)
#pragma unroll
            for (int h = 0; h < 2; h++) {
                size_t o = aoff[t][h] + ks * 64;
                a_[0][t][h] = *(const float2*)(Ah + o);
                a_[1][t][h] = *(const float2*)(Al + o);
            }
        float2 b_[2][NT];
#pragma unroll
        for (int nt = 0; nt < NT; nt++) {
            size_t o = boff[nt] + ks * 64;
            b_[0][nt] = *(const float2*)(Wh + o);
            b_[1][nt] = *(const float2*)(Wl + o);
        }
        uint32_t fa[2][2][4];
#pragma unroll
        for (int pl = 0; pl < 2; pl++)
#pragma unroll
            for (int t = 0; t < 2; t++) {
                fa[pl][t][0] = __float_as_uint(a_[pl][t][0].x);
                fa[pl][t][1] = __float_as_uint(a_[pl][t][1].x);
                fa[pl][t][2] = __float_as_uint(a_[pl][t][0].y);
                fa[pl][t][3] = __float_as_uint(a_[pl][t][1].y);
            }
#pragma unroll
        for (int nt = 0; nt < NT; nt++) {
            uint32_t bh0 = __float_as_uint(b_[0][nt].x);
            uint32_t bh1 = __float_as_uint(b_[0][nt].y);
            uint32_t bl0 = __float_as_uint(b_[1][nt].x);
            uint32_t bl1 = __float_as_uint(b_[1][nt].y);
#pragma unroll
            for (int t = 0; t < 2; t++) {
                mma8(c[t][nt], fa[0][t], bh0, bh1);   // hi*hi
                mma8(c[t][nt], fa[0][t], bl0, bl1);   // hi*lo
                mma8(c[t][nt], fa[1][t], bh0, bh1);   // lo*hi
            }
        }
    }

    // ---- epilogue: store H, fold attention dots ----
    float sa[4] = {0.f, 0.f, 0.f, 0.f};
    float sd[4] = {0.f, 0.f, 0.f, 0.f};
#pragma unroll
    for (int nt = 0; nt < NT; nt++) {
        int col0 = wn * (BN / 4) + nt * 8 + 2 * lk;
        float as_ = __ldg(a_s + col0), as1 = __ldg(a_s + col0 + 1);
        float ad_ = __ldg(a_d + col0), ad1 = __ldg(a_d + col0 + 1);
#pragma unroll
        for (int t = 0; t < 2; t++) {
            int rA = row0 + wm * 32 + t * 16 + lr;
            if (rA < M)
                *(float2*)(H + (size_t)rA * BN + col0) = make_float2(c[t][nt][0], c[t][nt][1]);
            if (rA + 8 < M)
                *(float2*)(H + (size_t)(rA + 8) * BN + col0) = make_float2(c[t][nt][2], c[t][nt][3]);
            sa[t * 2 + 0] += c[t][nt][0] * as_ + c[t][nt][1] * as1;
            sa[t * 2 + 1] += c[t][nt][2] * as_ + c[t][nt][3] * as1;
            sd[t * 2 + 0] += c[t][nt][0] * ad_ + c[t][nt][1] * ad1;
            sd[t * 2 + 1] += c[t][nt][2] * ad_ + c[t][nt][3] * ad1;
        }
    }
#pragma unroll
    for (int q = 0; q < 4; q++) {
        sa[q] += __shfl_xor_sync(0xffffffffu, sa[q], 1);
        sa[q] += __shfl_xor_sync(0xffffffffu, sa[q], 2);
        sd[q] += __shfl_xor_sync(0xffffffffu, sd[q], 1);
        sd[q] += __shfl_xor_sync(0xffffffffu, sd[q], 2);
    }
    __syncthreads();  // s_sa init visible
    if (lk == 0) {
#pragma unroll
        for (int t = 0; t < 2; t++) {
            int rl = wm * 32 + t * 16 + lr;
            atomicAdd(&s_sa[rl], sa[t * 2 + 0]);
            atomicAdd(&s_sd[rl], sd[t * 2 + 0]);
            atomicAdd(&s_sa[rl + 8], sa[t * 2 + 1]);
            atomicAdd(&s_sd[rl + 8], sd[t * 2 + 1]);
        }
    }
    __syncthreads();
    if (tid < 64) {
        int r = row0 + tid;
        if (r < M) {
            g_as[r] = s_sa[tid];
            g_ad[r] = s_sd[tid];
        }
    }
}

// ============ warp-per-dst-node segment softmax + weighted gather ============
// SPLIT: write tf32 hi/lo fragment-major planes (feeds next GEMM).

template <int D, bool SILU, bool SPLIT>
__global__ void k_agg(const float* __restrict__ h, const float* __restrict__ bias,
                      float* __restrict__ out, float* __restrict__ oh,
                      float* __restrict__ ol, int n) {
    constexpr int MAXDEG = 128;
    constexpr int FP = D / 32;  // floats per lane (4 or 2)
    __shared__ float wsh[8][MAXDEG];
    __shared__ int ssh[8][MAXDEG];
    int warp = threadIdx.x >> 5, lane = threadIdx.x & 31;
    int d = blockIdx.x * 8 + warp;
    if (d >= n) return;
    int st = g_start[d];
    int deg = g_deg[d] + 1;
    float ad = g_ad[d];
    int f = lane * FP;
    float acc[FP];
#pragma unroll
    for (int j = 0; j < FP; j++) acc[j] = 0.f;
    float inv;

    if (deg <= MAXDEG) {
        float m = -1e30f;
        for (int i = lane; i < deg; i += 32) {
            int s = g_csr[st + i];
            ssh[warp][i] = s;
            float al = g_as[s] + ad;
            al = al > 0.f ? al : NSLOPE * al;
            wsh[warp][i] = al;
            m = fmaxf(m, al);
        }
#pragma unroll
        for (int o = 16; o; o >>= 1) m = fmaxf(m, __shfl_xor_sync(0xffffffffu, m, o));
        __syncwarp();
        float den = 0.f;
        for (int i = lane; i < deg; i += 32) {
            float w = __expf(wsh[warp][i] - m);
            wsh[warp][i] = w;
            den += w;
        }
#pragma unroll
        for (int o = 16; o; o >>= 1) den += __shfl_xor_sync(0xffffffffu, den, o);
        __syncwarp();
        inv = 1.f / den;
        int i = 0;
        for (; i + 2 <= deg; i += 2) {
            int s0 = ssh[warp][i];
            int s1 = ssh[warp][i + 1];
            float c0 = wsh[warp][i];
            float c1 = wsh[warp][i + 1];
            const float* h0 = h + (size_t)s0 * D + f;
            const float* h1 = h + (size_t)s1 * D + f;
            if constexpr (FP == 4) {
                float4 v0 = *(const float4*)h0;
                float4 v1 = *(const float4*)h1;
                acc[0] += c0 * v0.x + c1 * v1.x;
                acc[1] += c0 * v0.y + c1 * v1.y;
                acc[2] += c0 * v0.z + c1 * v1.z;
                acc[3] += c0 * v0.w + c1 * v1.w;
            } else {
                float2 v0 = *(const float2*)h0;
                float2 v1 = *(const float2*)h1;
                acc[0] += c0 * v0.x + c1 * v1.x;
                acc[1] += c0 * v0.y + c1 * v1.y;
            }
        }
        if (i < deg) {
            int s0 = ssh[warp][i];
            float c0 = wsh[warp][i];
            const float* h0 = h + (size_t)s0 * D + f;
            if constexpr (FP == 4) {
                float4 v0 = *(const float4*)h0;
                acc[0] += c0 * v0.x;
                acc[1] += c0 * v0.y;
                acc[2] += c0 * v0.z;
                acc[3] += c0 * v0.w;
            } else {
                float2 v0 = *(const float2*)h0;
                acc[0] += c0 * v0.x;
                acc[1] += c0 * v0.y;
            }
        }
    } else {
        float m = -1e30f, den = 0.f;
        for (int i = 0; i < deg; i++) {
            int s = g_csr[st + i];
            float al = g_as[s] + ad;
            al = al > 0.f ? al : NSLOPE * al;
            float nm = fmaxf(m, al);
            float sc = __expf(m - nm);
            float w = __expf(al - nm);
            den = den * sc + w;
            const float* hp = h + (size_t)s * D + f;
#pragma unroll
            for (int j = 0; j < FP; j++) acc[j] = acc[j] * sc + w * hp[j];
            m = nm;
        }
        inv = 1.f / den;
    }

    float ov[FP];
#pragma unroll
    for (int j = 0; j < FP; j++) {
        float v = acc[j] * inv + bias[f + j];
        if (SILU) v = v / (1.f + __expf(-v));
        ov[j] = v;
    }

    if constexpr (SPLIT) {
        // fragment-major hi/lo planes: group g = lane>>1, slots lane-paired
        float nv[FP];
#pragma unroll
        for (int j = 0; j < FP; j++) nv[j] = __shfl_down_sync(0xffffffffu, ov[j], 1);
        if ((lane & 1) == 0) {
            float o8[8] = {ov[0], nv[0], ov[1], nv[1], ov[2], nv[2], ov[3], nv[3]};
            float hi[8], lo[8];
#pragma unroll
            for (int j = 0; j < 8; j++) split2(o8[j], hi[j], lo[j]);
            size_t o = ((size_t)(d >> 3) * 16 + (lane >> 1)) * 64 + (d & 7) * 8;
            *(float4*)(oh + o)     = make_float4(hi[0], hi[1], hi[2], hi[3]);
            *(float4*)(oh + o + 4) = make_float4(hi[4], hi[5], hi[6], hi[7]);
            *(float4*)(ol + o)     = make_float4(lo[0], lo[1], lo[2], lo[3]);
            *(float4*)(ol + o + 4) = make_float4(lo[4], lo[5], lo[6], lo[7]);
        }
    } else {
#pragma unroll
        for (int j = 0; j < FP; j++) out[(size_t)d * D + f + j] = ov[j];
    }
}

// ========================== log_softmax over 64 cols ==========================

__global__ void k_lsm(const float* __restrict__ in, float* __restrict__ out, int n) {
    int warp = threadIdx.x >> 5, lane = threadIdx.x & 31;
    int r = blockIdx.x * 8 + warp;
    if (r >= n) return;
    float2 v = *(const float2*)&in[(size_t)r * 64 + lane * 2];
    float m = fmaxf(v.x, v.y);
#pragma unroll
    for (int o = 16; o; o >>= 1) m = fmaxf(m, __shfl_xor_sync(0xffffffffu, m, o));
    float s = __expf(v.x - m) + __expf(v.y - m);
#pragma unroll
    for (int o = 16; o; o >>= 1) s += __shfl_xor_sync(0xffffffffu, s, o);
    float l = m + __logf(s);
    float2 o2 = make_float2(v.x - l, v.y - l);
    *(float2*)&out[(size_t)r * 64 + lane * 2] = o2;
}

// ========================== host launcher ==========================

extern "C" void kernel_launch(void* const* d_in, const int* in_sizes, int n_in,
                              void* d_out, int out_size) {
    const float* x   = (const float*)d_in[0];
    const int*   ei  = (const int*)d_in[1];
    const float* W0  = (const float*)d_in[2];
    const float* as0 = (const float*)d_in[3];
    const float* ad0 = (const float*)d_in[4];
    const float* b0  = (const float*)d_in[5];
    const float* W1  = (const float*)d_in[6];
    const float* as1 = (const float*)d_in[7];
    const float* ad1 = (const float*)d_in[8];
    const float* b1  = (const float*)d_in[9];
    const float* W2  = (const float*)d_in[10];
    const float* as2 = (const float*)d_in[11];
    const float* ad2 = (const float*)d_in[12];
    const float* b2  = (const float*)d_in[13];

    int n = in_sizes[0] / 128;  // 50000
    int e = in_sizes[1] / 2;    // 600000
    const int* src = ei;
    const int* dst = ei + e;
    float* outp = (float*)d_out;

    float *ph, *pah, *pal, *pwh, *pwl, *po2;
    cudaGetSymbolAddress((void**)&ph, g_h);
    cudaGetSymbolAddress((void**)&pah, g_ahp);
    cudaGetSymbolAddress((void**)&pal, g_alp);
    cudaGetSymbolAddress((void**)&pwh, g_wh);
    cudaGetSymbolAddress((void**)&pwl, g_wl);
    cudaGetSymbolAddress((void**)&po2, g_o2);

    int nbN = (n + 255) / 256;
    int nbE = (e + 255) / 256;
    int nbC = (n * 16 + 255) / 256;
    int nbW128 = (128 * 128 + 255) / 256;
    int nbW64  = (128 * 64 + 255) / 256;
    int nbG = (n + 63) / 64;
    int nbA = (n + 7) / 8;
    int nbL = (n + 7) / 8;

    // launch order keeps k_tc<128> in the ncu capture slot
    k_cvt<<<nbC, 256>>>(x, pah, pal, n);
    k_wcvt<<<nbW128, 256>>>(W0, pwh, pwl, 128);
    k_zero<<<nbN, 256>>>(n);
    k_tc<128><<<nbG, 256>>>(pah, pal, pwh, pwl, ph, as0, ad0, n);  // layer 0
    k_count<<<nbE, 256>>>(dst, e);
    k_alloc<<<nbN, 256>>>(n);
    k_scatter<<<nbE, 256>>>(src, dst, e);
    k_wcvt<<<nbW128, 256>>>(W1, pwh + 16384, pwl + 16384, 128);
    k_agg<128, true, true><<<nbA, 256>>>(ph, b0, nullptr, pah, pal, n);

    // layer 1
    k_tc<128><<<nbG, 256>>>(pah, pal, pwh + 16384, pwl + 16384, ph, as1, ad1, n);
    k_wcvt<<<nbW64, 256>>>(W2, pwh + 32768, pwl + 32768, 64);
    k_agg<128, true, true><<<nbA, 256>>>(ph, b1, nullptr, pah, pal, n);

    // layer 2: 128 -> 64
    k_tc<64><<<nbG, 256>>>(pah, pal, pwh + 32768, pwl + 32768, ph, as2, ad2, n);
    k_agg<64, false, false><<<nbA, 256>>>(ph, b2, po2, nullptr, nullptr, n);
    k_lsm<<<nbL, 256>>>(po2, outp, n);
}